// round 3
// baseline (speedup 1.0000x reference)
#include <cuda_runtime.h>
#include <cuda_bf16.h>
#include <math.h>

#define NODES 50000
#define EDGES 800000
#define DIM   64

// Scratch (no allocation allowed in kernel_launch)
__device__ float g_agg[NODES * DIM];   // 12.8 MB
__device__ float g_h  [NODES * DIM];   // 12.8 MB
__device__ float g_cnt[NODES];         // 200 KB

// ---------------------------------------------------------------------------
// Zero scratch: agg always; cnt only when requested
// ---------------------------------------------------------------------------
__global__ void zero_kernel(int zero_cnt) {
    int total = NODES * DIM + (zero_cnt ? NODES : 0);
    for (int i = blockIdx.x * blockDim.x + threadIdx.x; i < total;
         i += gridDim.x * blockDim.x) {
        if (i < NODES * DIM) g_agg[i] = 0.0f;
        else                 g_cnt[i - NODES * DIM] = 0.0f;
    }
}

// ---------------------------------------------------------------------------
// Scatter: for each edge, agg[dst] += feat[src]  (+ cnt[dst] += 1 first pass)
// Half-warp per edge: 16 lanes x float4 = one contiguous 256B row.
// Index load is uniform across the 16 lanes -> single broadcast request.
// edge_index arrives as int32 (harness converts int64 -> int32).
// ---------------------------------------------------------------------------
__global__ void scatter_kernel(const float* __restrict__ feat,
                               const int* __restrict__ ei,
                               int do_count) {
    long long t = (long long)blockIdx.x * blockDim.x + threadIdx.x;
    if (t >= (long long)EDGES * 16) return;
    int e = (int)(t >> 4);
    int c = (int)(t & 15);

    int src = __ldg(&ei[e]);
    int dst = __ldg(&ei[EDGES + e]);
    if ((unsigned)src >= NODES || (unsigned)dst >= NODES) return; // safety

    float4 v = __ldg(((const float4*)(feat + (size_t)src * DIM)) + c);

    float4* dstp = ((float4*)(g_agg + (size_t)dst * DIM)) + c;
#if defined(__CUDA_ARCH__) && (__CUDA_ARCH__ >= 900)
    atomicAdd(dstp, v);
#else
    float* dp = (float*)dstp;
    atomicAdd(dp + 0, v.x);
    atomicAdd(dp + 1, v.y);
    atomicAdd(dp + 2, v.z);
    atomicAdd(dp + 3, v.w);
#endif
    if (do_count && c == 0) atomicAdd(&g_cnt[dst], 1.0f);
}

// ---------------------------------------------------------------------------
// Node transform: out[n] = (agg[n]/max(cnt,1)) @ Wl^T + b + in[n] @ Wr^T
// 16 nodes per 256-thread block. W stored transposed in shared with pitch 65
// (conflict-free: lane d reads s_W[k*65 + d]).
// smem: 2*64*65*4 + 2*16*64*4 = 41,472 B < 48 KB static cap.
// ---------------------------------------------------------------------------
#define TNODES 16

template <bool APPLY_TANH>
__global__ void transform_kernel(const float* __restrict__ agg,
                                 const float* __restrict__ xin,
                                 const float* __restrict__ Wl,
                                 const float* __restrict__ bl,
                                 const float* __restrict__ Wr,
                                 float* __restrict__ out) {
    __shared__ float s_Wl[DIM * 65];
    __shared__ float s_Wr[DIM * 65];
    __shared__ float s_a[TNODES * DIM];
    __shared__ float s_x[TNODES * DIM];

    int tid = threadIdx.x;            // 256 threads
    // Load weights transposed: W[d][k] -> s_W[k*65 + d]
    for (int i = tid; i < DIM * DIM; i += 256) {
        int d = i >> 6, k = i & 63;
        s_Wl[k * 65 + d] = __ldg(&Wl[i]);
        s_Wr[k * 65 + d] = __ldg(&Wr[i]);
    }

    int n0 = blockIdx.x * TNODES;
    for (int i = tid; i < TNODES * DIM; i += 256) {
        int nl = i >> 6;
        int n  = n0 + nl;
        if (n < NODES) {
            float inv = 1.0f / fmaxf(g_cnt[n], 1.0f);
            s_a[i] = agg[(size_t)n * DIM + (i & 63)] * inv;
            s_x[i] = xin[(size_t)n * DIM + (i & 63)];
        }
    }
    __syncthreads();

    int d  = tid & 63;
    int ng = tid >> 6;                // 0..3
    float bias = __ldg(&bl[d]);

    for (int nl = ng; nl < TNODES; nl += 4) {
        int n = n0 + nl;
        if (n >= NODES) break;
        float acc = bias;
        const float* ar = &s_a[nl * DIM];
        const float* xr = &s_x[nl * DIM];
#pragma unroll
        for (int k = 0; k < DIM; k++) {
            acc += ar[k] * s_Wl[k * 65 + d];
            acc += xr[k] * s_Wr[k * 65 + d];
        }
        if (APPLY_TANH) acc = tanhf(acc);
        out[(size_t)n * DIM + d] = acc;
    }
}

// ---------------------------------------------------------------------------
// Launch
// ---------------------------------------------------------------------------
extern "C" void kernel_launch(void* const* d_in, const int* in_sizes, int n_in,
                              void* d_out, int out_size) {
    const float* x    = (const float*)d_in[0];
    const int*   ei   = (const int*)d_in[1];
    const float* W_l1 = (const float*)d_in[2];
    const float* b_l1 = (const float*)d_in[3];
    const float* W_r1 = (const float*)d_in[4];
    const float* W_l2 = (const float*)d_in[5];
    const float* b_l2 = (const float*)d_in[6];
    const float* W_r2 = (const float*)d_in[7];
    float* out = (float*)d_out;

    float* agg; cudaGetSymbolAddress((void**)&agg, g_agg);
    float* h;   cudaGetSymbolAddress((void**)&h,   g_h);

    const int ZB = 256, ZG = (NODES * DIM + NODES + ZB - 1) / ZB;
    const long long st = (long long)EDGES * 16;
    const int SB = 256;
    const int SG = (int)((st + SB - 1) / SB);
    const int TG = (NODES + TNODES - 1) / TNODES;

    // Layer 1
    zero_kernel<<<ZG, ZB>>>(1);
    scatter_kernel<<<SG, SB>>>(x, ei, 1);
    transform_kernel<true><<<TG, 256>>>(agg, x, W_l1, b_l1, W_r1, h);

    // Layer 2 (counts reused)
    zero_kernel<<<ZG, ZB>>>(0);
    scatter_kernel<<<SG, SB>>>(h, ei, 0);
    transform_kernel<false><<<TG, 256>>>(agg, h, W_l2, b_l2, W_r2, out);
}

// round 4
// speedup vs baseline: 1.2183x; 1.2183x over previous
#include <cuda_runtime.h>
#include <cuda_bf16.h>
#include <math.h>

#define NODES 50000
#define EDGES 800000
#define DIM   64

#define SCAN_B 512
#define NB ((NODES + SCAN_B - 1) / SCAN_B)   // 98

// Scratch (no allocation allowed in kernel_launch)
__device__ float g_agg[NODES * DIM];     // 12.8 MB (mean-aggregated)
__device__ float g_h  [NODES * DIM];     // 12.8 MB
__device__ int   g_deg[NODES];
__device__ int   g_rowptr[NODES + 1];
__device__ int   g_cursor[NODES];
__device__ int   g_col[EDGES];           // 3.2 MB
__device__ int   g_bsum[NB];
__device__ int   g_boff[NB];

// ---------------------------------------------------------------------------
// CSR build: histogram -> block scan (3 kernels) -> fill
// ---------------------------------------------------------------------------
__global__ void zero_deg_kernel() {
    int i = blockIdx.x * blockDim.x + threadIdx.x;
    if (i < NODES) g_deg[i] = 0;
}

__global__ void hist_kernel(const int* __restrict__ ei) {
    int e = blockIdx.x * blockDim.x + threadIdx.x;
    if (e >= EDGES) return;
    int dst = __ldg(&ei[EDGES + e]);
    if ((unsigned)dst < NODES) atomicAdd(&g_deg[dst], 1);
}

__global__ void scanA_kernel() {        // per-block degree sums
    __shared__ int s[SCAN_B];
    int i = blockIdx.x * SCAN_B + threadIdx.x;
    s[threadIdx.x] = (i < NODES) ? g_deg[i] : 0;
    __syncthreads();
    for (int off = SCAN_B / 2; off > 0; off >>= 1) {
        if (threadIdx.x < off) s[threadIdx.x] += s[threadIdx.x + off];
        __syncthreads();
    }
    if (threadIdx.x == 0) g_bsum[blockIdx.x] = s[0];
}

__global__ void scanB_kernel() {        // exclusive scan of NB block sums
    __shared__ int s[NB];
    if (threadIdx.x < NB) s[threadIdx.x] = g_bsum[threadIdx.x];
    __syncthreads();
    if (threadIdx.x == 0) {
        int acc = 0;
        for (int b = 0; b < NB; b++) { int v = s[b]; s[b] = acc; acc += v; }
    }
    __syncthreads();
    if (threadIdx.x < NB) g_boff[threadIdx.x] = s[threadIdx.x];
}

__global__ void scanC_kernel() {        // per-block inclusive scan + offset
    __shared__ int s[SCAN_B];
    int i = blockIdx.x * SCAN_B + threadIdx.x;
    int d = (i < NODES) ? g_deg[i] : 0;
    s[threadIdx.x] = d;
    __syncthreads();
    // Hillis-Steele inclusive scan
    for (int off = 1; off < SCAN_B; off <<= 1) {
        int v = (threadIdx.x >= off) ? s[threadIdx.x - off] : 0;
        __syncthreads();
        s[threadIdx.x] += v;
        __syncthreads();
    }
    if (i < NODES) {
        int excl = g_boff[blockIdx.x] + s[threadIdx.x] - d;
        g_rowptr[i] = excl;
        g_cursor[i] = excl;
        if (i == NODES - 1) g_rowptr[NODES] = g_boff[blockIdx.x] + s[threadIdx.x];
    }
}

__global__ void fill_kernel(const int* __restrict__ ei) {
    int e = blockIdx.x * blockDim.x + threadIdx.x;
    if (e >= EDGES) return;
    int src = __ldg(&ei[e]);
    int dst = __ldg(&ei[EDGES + e]);
    if ((unsigned)src >= NODES || (unsigned)dst >= NODES) return;
    int p = atomicAdd(&g_cursor[dst], 1);
    g_col[p] = src;
}

// ---------------------------------------------------------------------------
// Gather aggregation: half-warp (16 lanes) per dst node, lane c owns float4
// chunk c. Register accumulation; no atomics, no zero pass. Mean applied here.
// 4-way unrolled neighbor loop for MLP against L2 latency.
// ---------------------------------------------------------------------------
__global__ void gather_kernel(const float* __restrict__ feat) {
    long long t = (long long)blockIdx.x * blockDim.x + threadIdx.x;
    if (t >= (long long)NODES * 16) return;
    int node = (int)(t >> 4);
    int c    = (int)(t & 15);

    int start = __ldg(&g_rowptr[node]);
    int end   = __ldg(&g_rowptr[node + 1]);

    float4 acc = make_float4(0.f, 0.f, 0.f, 0.f);
    int p = start;
    for (; p + 4 <= end; p += 4) {
        int s0 = __ldg(&g_col[p + 0]);
        int s1 = __ldg(&g_col[p + 1]);
        int s2 = __ldg(&g_col[p + 2]);
        int s3 = __ldg(&g_col[p + 3]);
        float4 v0 = __ldg(((const float4*)(feat + (size_t)s0 * DIM)) + c);
        float4 v1 = __ldg(((const float4*)(feat + (size_t)s1 * DIM)) + c);
        float4 v2 = __ldg(((const float4*)(feat + (size_t)s2 * DIM)) + c);
        float4 v3 = __ldg(((const float4*)(feat + (size_t)s3 * DIM)) + c);
        acc.x += v0.x + v1.x + v2.x + v3.x;
        acc.y += v0.y + v1.y + v2.y + v3.y;
        acc.z += v0.z + v1.z + v2.z + v3.z;
        acc.w += v0.w + v1.w + v2.w + v3.w;
    }
    for (; p < end; p++) {
        int s = __ldg(&g_col[p]);
        float4 v = __ldg(((const float4*)(feat + (size_t)s * DIM)) + c);
        acc.x += v.x; acc.y += v.y; acc.z += v.z; acc.w += v.w;
    }

    float inv = 1.0f / fmaxf((float)(end - start), 1.0f);
    acc.x *= inv; acc.y *= inv; acc.z *= inv; acc.w *= inv;
    ((float4*)(g_agg + (size_t)node * DIM))[c] = acc;
}

// ---------------------------------------------------------------------------
// Node transform: out[n] = agg[n] @ Wl^T + b + in[n] @ Wr^T
// (agg already mean-divided.) 24 nodes / 256-thread block.
// smem: 2*64*65*4 + 2*24*64*4 = 45,568 B < 48 KB static cap.
// ---------------------------------------------------------------------------
#define TNODES 24

template <bool APPLY_TANH>
__global__ void transform_kernel(const float* __restrict__ agg,
                                 const float* __restrict__ xin,
                                 const float* __restrict__ Wl,
                                 const float* __restrict__ bl,
                                 const float* __restrict__ Wr,
                                 float* __restrict__ out) {
    __shared__ float s_Wl[DIM * 65];
    __shared__ float s_Wr[DIM * 65];
    __shared__ float s_a[TNODES * DIM];
    __shared__ float s_x[TNODES * DIM];

    int tid = threadIdx.x;            // 256 threads
    for (int i = tid; i < DIM * DIM; i += 256) {
        int d = i >> 6, k = i & 63;
        s_Wl[k * 65 + d] = __ldg(&Wl[i]);
        s_Wr[k * 65 + d] = __ldg(&Wr[i]);
    }

    int n0 = blockIdx.x * TNODES;
    for (int i = tid; i < TNODES * DIM; i += 256) {
        int n = n0 + (i >> 6);
        if (n < NODES) {
            s_a[i] = agg[(size_t)n * DIM + (i & 63)];
            s_x[i] = xin[(size_t)n * DIM + (i & 63)];
        }
    }
    __syncthreads();

    int d  = tid & 63;
    int ng = tid >> 6;                // 0..3
    float bias = __ldg(&bl[d]);

    for (int nl = ng; nl < TNODES; nl += 4) {
        int n = n0 + nl;
        if (n >= NODES) break;
        float acc = bias;
        const float* ar = &s_a[nl * DIM];
        const float* xr = &s_x[nl * DIM];
#pragma unroll
        for (int k = 0; k < DIM; k++) {
            acc += ar[k] * s_Wl[k * 65 + d];
            acc += xr[k] * s_Wr[k * 65 + d];
        }
        if (APPLY_TANH) acc = tanhf(acc);
        out[(size_t)n * DIM + d] = acc;
    }
}

// ---------------------------------------------------------------------------
// Launch
// ---------------------------------------------------------------------------
extern "C" void kernel_launch(void* const* d_in, const int* in_sizes, int n_in,
                              void* d_out, int out_size) {
    const float* x    = (const float*)d_in[0];
    const int*   ei   = (const int*)d_in[1];
    const float* W_l1 = (const float*)d_in[2];
    const float* b_l1 = (const float*)d_in[3];
    const float* W_r1 = (const float*)d_in[4];
    const float* W_l2 = (const float*)d_in[5];
    const float* b_l2 = (const float*)d_in[6];
    const float* W_r2 = (const float*)d_in[7];
    float* out = (float*)d_out;

    float* agg; cudaGetSymbolAddress((void**)&agg, g_agg);
    float* h;   cudaGetSymbolAddress((void**)&h,   g_h);

    const int EB = 256, EG = (EDGES + EB - 1) / EB;
    const int GG = (int)(((long long)NODES * 16 + 255) / 256);
    const int TG = (NODES + TNODES - 1) / TNODES;

    // CSR build (once; reused by both layers)
    zero_deg_kernel<<<(NODES + 255) / 256, 256>>>();
    hist_kernel<<<EG, EB>>>(ei);
    scanA_kernel<<<NB, SCAN_B>>>();
    scanB_kernel<<<1, 128>>>();
    scanC_kernel<<<NB, SCAN_B>>>();
    fill_kernel<<<EG, EB>>>(ei);

    // Layer 1
    gather_kernel<<<GG, 256>>>(x);
    transform_kernel<true><<<TG, 256>>>(agg, x, W_l1, b_l1, W_r1, h);

    // Layer 2
    gather_kernel<<<GG, 256>>>(h);
    transform_kernel<false><<<TG, 256>>>(agg, h, W_l2, b_l2, W_r2, out);
}

// round 5
// speedup vs baseline: 1.9145x; 1.5714x over previous
#include <cuda_runtime.h>
#include <cuda_bf16.h>
#include <math.h>

#define NODES 50000
#define EDGES 800000
#define DIM   64

#define SCAN_B 512
#define NB ((NODES + SCAN_B - 1) / SCAN_B)   // 98

// Scratch (no allocation allowed in kernel_launch)
__device__ float g_agg[NODES * DIM];     // 12.8 MB (mean-aggregated)
__device__ float g_h  [NODES * DIM];     // 12.8 MB
__device__ int   g_deg[NODES];
__device__ int   g_rowptr[NODES + 1];
__device__ int   g_cursor[NODES];
__device__ int   g_col[EDGES];           // 3.2 MB
__device__ int   g_bsum[NB];
__device__ int   g_boff[NB];

// ---------------------------------------------------------------------------
// CSR build: histogram -> block scan (3 kernels) -> fill
// ---------------------------------------------------------------------------
__global__ void zero_deg_kernel() {
    int i = blockIdx.x * blockDim.x + threadIdx.x;
    if (i < NODES) g_deg[i] = 0;
}

__global__ void hist_kernel(const int* __restrict__ ei) {
    int e = blockIdx.x * blockDim.x + threadIdx.x;
    if (e >= EDGES) return;
    int dst = __ldg(&ei[EDGES + e]);
    if ((unsigned)dst < NODES) atomicAdd(&g_deg[dst], 1);
}

__global__ void scanA_kernel() {        // per-block degree sums
    __shared__ int s[SCAN_B];
    int i = blockIdx.x * SCAN_B + threadIdx.x;
    s[threadIdx.x] = (i < NODES) ? g_deg[i] : 0;
    __syncthreads();
    for (int off = SCAN_B / 2; off > 0; off >>= 1) {
        if (threadIdx.x < off) s[threadIdx.x] += s[threadIdx.x + off];
        __syncthreads();
    }
    if (threadIdx.x == 0) g_bsum[blockIdx.x] = s[0];
}

__global__ void scanB_kernel() {        // exclusive scan of NB block sums
    __shared__ int s[NB];
    if (threadIdx.x < NB) s[threadIdx.x] = g_bsum[threadIdx.x];
    __syncthreads();
    if (threadIdx.x == 0) {
        int acc = 0;
        for (int b = 0; b < NB; b++) { int v = s[b]; s[b] = acc; acc += v; }
    }
    __syncthreads();
    if (threadIdx.x < NB) g_boff[threadIdx.x] = s[threadIdx.x];
}

__global__ void scanC_kernel() {        // per-block inclusive scan + offset
    __shared__ int s[SCAN_B];
    int i = blockIdx.x * SCAN_B + threadIdx.x;
    int d = (i < NODES) ? g_deg[i] : 0;
    s[threadIdx.x] = d;
    __syncthreads();
    for (int off = 1; off < SCAN_B; off <<= 1) {
        int v = (threadIdx.x >= off) ? s[threadIdx.x - off] : 0;
        __syncthreads();
        s[threadIdx.x] += v;
        __syncthreads();
    }
    if (i < NODES) {
        int excl = g_boff[blockIdx.x] + s[threadIdx.x] - d;
        g_rowptr[i] = excl;
        g_cursor[i] = excl;
        if (i == NODES - 1) g_rowptr[NODES] = g_boff[blockIdx.x] + s[threadIdx.x];
    }
}

__global__ void fill_kernel(const int* __restrict__ ei) {
    int e = blockIdx.x * blockDim.x + threadIdx.x;
    if (e >= EDGES) return;
    int src = __ldg(&ei[e]);
    int dst = __ldg(&ei[EDGES + e]);
    if ((unsigned)src >= NODES || (unsigned)dst >= NODES) return;
    int p = atomicAdd(&g_cursor[dst], 1);
    g_col[p] = src;
}

// ---------------------------------------------------------------------------
// Gather aggregation: half-warp (16 lanes) per dst node, lane c owns float4
// chunk c. Register accumulation; no atomics. Mean applied here.
// 8-way unrolled neighbor loop for MLP against L2 latency.
// ---------------------------------------------------------------------------
__global__ void gather_kernel(const float* __restrict__ feat) {
    long long t = (long long)blockIdx.x * blockDim.x + threadIdx.x;
    if (t >= (long long)NODES * 16) return;
    int node = (int)(t >> 4);
    int c    = (int)(t & 15);

    int start = __ldg(&g_rowptr[node]);
    int end   = __ldg(&g_rowptr[node + 1]);

    float4 acc = make_float4(0.f, 0.f, 0.f, 0.f);
    int p = start;
    for (; p + 8 <= end; p += 8) {
        int s0 = __ldg(&g_col[p + 0]);
        int s1 = __ldg(&g_col[p + 1]);
        int s2 = __ldg(&g_col[p + 2]);
        int s3 = __ldg(&g_col[p + 3]);
        int s4 = __ldg(&g_col[p + 4]);
        int s5 = __ldg(&g_col[p + 5]);
        int s6 = __ldg(&g_col[p + 6]);
        int s7 = __ldg(&g_col[p + 7]);
        float4 v0 = __ldg(((const float4*)(feat + (size_t)s0 * DIM)) + c);
        float4 v1 = __ldg(((const float4*)(feat + (size_t)s1 * DIM)) + c);
        float4 v2 = __ldg(((const float4*)(feat + (size_t)s2 * DIM)) + c);
        float4 v3 = __ldg(((const float4*)(feat + (size_t)s3 * DIM)) + c);
        float4 v4 = __ldg(((const float4*)(feat + (size_t)s4 * DIM)) + c);
        float4 v5 = __ldg(((const float4*)(feat + (size_t)s5 * DIM)) + c);
        float4 v6 = __ldg(((const float4*)(feat + (size_t)s6 * DIM)) + c);
        float4 v7 = __ldg(((const float4*)(feat + (size_t)s7 * DIM)) + c);
        acc.x += (v0.x + v1.x) + (v2.x + v3.x) + (v4.x + v5.x) + (v6.x + v7.x);
        acc.y += (v0.y + v1.y) + (v2.y + v3.y) + (v4.y + v5.y) + (v6.y + v7.y);
        acc.z += (v0.z + v1.z) + (v2.z + v3.z) + (v4.z + v5.z) + (v6.z + v7.z);
        acc.w += (v0.w + v1.w) + (v2.w + v3.w) + (v4.w + v5.w) + (v6.w + v7.w);
    }
    for (; p < end; p++) {
        int s = __ldg(&g_col[p]);
        float4 v = __ldg(((const float4*)(feat + (size_t)s * DIM)) + c);
        acc.x += v.x; acc.y += v.y; acc.z += v.z; acc.w += v.w;
    }

    float inv = 1.0f / fmaxf((float)(end - start), 1.0f);
    acc.x *= inv; acc.y *= inv; acc.z *= inv; acc.w *= inv;
    ((float4*)(g_agg + (size_t)node * DIM))[c] = acc;
}

// ---------------------------------------------------------------------------
// Node transform v2 (register-tiled):
//   out[n][d] = sum_k agg[n][k]*Wl[d][k] + b[d] + sum_k x[n][k]*Wr[d][k]
// 256 threads / 64 nodes per block. Thread = 4 nodes x 4 dims (16 acc).
// Weights transposed into smem with pitch 65 (conflict-free stage + read).
// Activations read directly from gmem as float4 along k (warp-broadcast,
// L1/L2-hit). FFMA-pipe bound.
// ---------------------------------------------------------------------------
#define TN 64

template <bool APPLY_TANH>
__global__ void __launch_bounds__(256) transform_kernel(
        const float* __restrict__ agg,
        const float* __restrict__ xin,
        const float* __restrict__ Wl,
        const float* __restrict__ bl,
        const float* __restrict__ Wr,
        float* __restrict__ out) {
    // sW[k*65 + d] : k in [0,64) -> Wl[d][k],  k in [64,128) -> Wr[d][k-64]
    __shared__ float sW[128 * 65];

    int tid = threadIdx.x;
    for (int i = tid; i < DIM * DIM; i += 256) {
        int dout = i >> 6, k = i & 63;          // i = dout*64 + k  (coalesced read)
        sW[k * 65 + dout]        = __ldg(&Wl[i]);   // stride-65 write: conflict-free
        sW[(64 + k) * 65 + dout] = __ldg(&Wr[i]);
    }
    __syncthreads();

    int dt = tid & 15;                  // 16 dim-groups
    int nt = tid >> 4;                  // 16 node-groups
    int d  = dt * 4;
    int n0 = blockIdx.x * TN + nt * 4;

    // Clamped row pointers so OOB threads still issue safe loads
    const float4* arow[4];
    const float4* xrow[4];
#pragma unroll
    for (int j = 0; j < 4; j++) {
        int n = n0 + j; if (n >= NODES) n = NODES - 1;
        arow[j] = (const float4*)(agg + (size_t)n * DIM);
        xrow[j] = (const float4*)(xin + (size_t)n * DIM);
    }

    float acc[4][4];
#pragma unroll
    for (int j = 0; j < 4; j++)
#pragma unroll
        for (int q = 0; q < 4; q++) acc[j][q] = 0.0f;

    // ---- agg @ Wl^T : k = 0..63 ----
#pragma unroll
    for (int kq = 0; kq < 16; kq++) {
        float4 a0 = __ldg(arow[0] + kq);
        float4 a1 = __ldg(arow[1] + kq);
        float4 a2 = __ldg(arow[2] + kq);
        float4 a3 = __ldg(arow[3] + kq);
        const float av[4][4] = {{a0.x,a0.y,a0.z,a0.w},{a1.x,a1.y,a1.z,a1.w},
                                {a2.x,a2.y,a2.z,a2.w},{a3.x,a3.y,a3.z,a3.w}};
#pragma unroll
        for (int kk = 0; kk < 4; kk++) {
            int k = kq * 4 + kk;
            float w0 = sW[k * 65 + d + 0];
            float w1 = sW[k * 65 + d + 1];
            float w2 = sW[k * 65 + d + 2];
            float w3 = sW[k * 65 + d + 3];
#pragma unroll
            for (int j = 0; j < 4; j++) {
                acc[j][0] += av[j][kk] * w0;
                acc[j][1] += av[j][kk] * w1;
                acc[j][2] += av[j][kk] * w2;
                acc[j][3] += av[j][kk] * w3;
            }
        }
    }
    // ---- x @ Wr^T : k = 64..127 (weights rows 64..127) ----
#pragma unroll
    for (int kq = 0; kq < 16; kq++) {
        float4 a0 = __ldg(xrow[0] + kq);
        float4 a1 = __ldg(xrow[1] + kq);
        float4 a2 = __ldg(xrow[2] + kq);
        float4 a3 = __ldg(xrow[3] + kq);
        const float av[4][4] = {{a0.x,a0.y,a0.z,a0.w},{a1.x,a1.y,a1.z,a1.w},
                                {a2.x,a2.y,a2.z,a2.w},{a3.x,a3.y,a3.z,a3.w}};
#pragma unroll
        for (int kk = 0; kk < 4; kk++) {
            int k = 64 + kq * 4 + kk;
            float w0 = sW[k * 65 + d + 0];
            float w1 = sW[k * 65 + d + 1];
            float w2 = sW[k * 65 + d + 2];
            float w3 = sW[k * 65 + d + 3];
#pragma unroll
            for (int j = 0; j < 4; j++) {
                acc[j][0] += av[j][kk] * w0;
                acc[j][1] += av[j][kk] * w1;
                acc[j][2] += av[j][kk] * w2;
                acc[j][3] += av[j][kk] * w3;
            }
        }
    }

    float b0 = __ldg(&bl[d + 0]);
    float b1 = __ldg(&bl[d + 1]);
    float b2 = __ldg(&bl[d + 2]);
    float b3 = __ldg(&bl[d + 3]);

#pragma unroll
    for (int j = 0; j < 4; j++) {
        int n = n0 + j;
        if (n >= NODES) break;
        float4 r;
        r.x = acc[j][0] + b0;
        r.y = acc[j][1] + b1;
        r.z = acc[j][2] + b2;
        r.w = acc[j][3] + b3;
        if (APPLY_TANH) {
            r.x = tanhf(r.x); r.y = tanhf(r.y);
            r.z = tanhf(r.z); r.w = tanhf(r.w);
        }
        ((float4*)(out + (size_t)n * DIM))[dt] = r;
    }
}

// ---------------------------------------------------------------------------
// Launch
// ---------------------------------------------------------------------------
extern "C" void kernel_launch(void* const* d_in, const int* in_sizes, int n_in,
                              void* d_out, int out_size) {
    const float* x    = (const float*)d_in[0];
    const int*   ei   = (const int*)d_in[1];
    const float* W_l1 = (const float*)d_in[2];
    const float* b_l1 = (const float*)d_in[3];
    const float* W_r1 = (const float*)d_in[4];
    const float* W_l2 = (const float*)d_in[5];
    const float* b_l2 = (const float*)d_in[6];
    const float* W_r2 = (const float*)d_in[7];
    float* out = (float*)d_out;

    float* agg; cudaGetSymbolAddress((void**)&agg, g_agg);
    float* h;   cudaGetSymbolAddress((void**)&h,   g_h);

    const int EB = 256, EG = (EDGES + EB - 1) / EB;
    const int GG = (int)(((long long)NODES * 16 + 255) / 256);
    const int TG = (NODES + TN - 1) / TN;

    // CSR build (once; reused by both layers)
    zero_deg_kernel<<<(NODES + 255) / 256, 256>>>();
    hist_kernel<<<EG, EB>>>(ei);
    scanA_kernel<<<NB, SCAN_B>>>();
    scanB_kernel<<<1, 128>>>();
    scanC_kernel<<<NB, SCAN_B>>>();
    fill_kernel<<<EG, EB>>>(ei);

    // Layer 1
    gather_kernel<<<GG, 256>>>(x);
    transform_kernel<true><<<TG, 256>>>(agg, x, W_l1, b_l1, W_r1, h);

    // Layer 2
    gather_kernel<<<GG, 256>>>(h);
    transform_kernel<false><<<TG, 256>>>(agg, h, W_l2, b_l2, W_r2, out);
}

// round 6
// speedup vs baseline: 2.0002x; 1.0448x over previous
#include <cuda_runtime.h>
#include <cuda_fp16.h>
#include <math.h>

#define NODES 50000
#define EDGES 800000
#define DIM   64

#define SCAN_B 512
#define NB ((NODES + SCAN_B - 1) / SCAN_B)   // 98

// Scratch (no allocation allowed in kernel_launch)
__device__ float  g_agg[NODES * DIM];    // 12.8 MB (mean-aggregated, fp32)
__device__ float  g_h  [NODES * DIM];    // 12.8 MB
__device__ __half g_x16[NODES * DIM];    // 6.4 MB  (fp16 message copies)
__device__ __half g_h16[NODES * DIM];    // 6.4 MB
__device__ int    g_deg[NODES];
__device__ int    g_rowptr[NODES + 1];
__device__ int    g_cursor[NODES];
__device__ int    g_col[EDGES];          // 3.2 MB
__device__ int    g_bsum[NB];
__device__ int    g_boff[NB];

// ---------------------------------------------------------------------------
// fp32 -> fp16 convert (x staging). 4 elems / thread.
// ---------------------------------------------------------------------------
__global__ void convert_kernel(const float* __restrict__ in) {
    int i = blockIdx.x * blockDim.x + threadIdx.x;      // quad index
    if (i >= NODES * DIM / 4) return;
    float4 v = __ldg(((const float4*)in) + i);
    __half2 h0 = __floats2half2_rn(v.x, v.y);
    __half2 h1 = __floats2half2_rn(v.z, v.w);
    ((__half2*)g_x16)[i * 2 + 0] = h0;
    ((__half2*)g_x16)[i * 2 + 1] = h1;
}

// ---------------------------------------------------------------------------
// CSR build: histogram -> block scan (3 kernels) -> fill
// ---------------------------------------------------------------------------
__global__ void zero_deg_kernel() {
    int i = blockIdx.x * blockDim.x + threadIdx.x;
    if (i < NODES) g_deg[i] = 0;
}

__global__ void hist_kernel(const int* __restrict__ ei) {
    int e = blockIdx.x * blockDim.x + threadIdx.x;
    if (e >= EDGES) return;
    int dst = __ldg(&ei[EDGES + e]);
    if ((unsigned)dst < NODES) atomicAdd(&g_deg[dst], 1);
}

__global__ void scanA_kernel() {        // per-block degree sums
    __shared__ int s[SCAN_B];
    int i = blockIdx.x * SCAN_B + threadIdx.x;
    s[threadIdx.x] = (i < NODES) ? g_deg[i] : 0;
    __syncthreads();
    for (int off = SCAN_B / 2; off > 0; off >>= 1) {
        if (threadIdx.x < off) s[threadIdx.x] += s[threadIdx.x + off];
        __syncthreads();
    }
    if (threadIdx.x == 0) g_bsum[blockIdx.x] = s[0];
}

__global__ void scanB_kernel() {        // exclusive scan of NB block sums
    __shared__ int s[NB];
    if (threadIdx.x < NB) s[threadIdx.x] = g_bsum[threadIdx.x];
    __syncthreads();
    if (threadIdx.x == 0) {
        int acc = 0;
        for (int b = 0; b < NB; b++) { int v = s[b]; s[b] = acc; acc += v; }
    }
    __syncthreads();
    if (threadIdx.x < NB) g_boff[threadIdx.x] = s[threadIdx.x];
}

__global__ void scanC_kernel() {        // per-block inclusive scan + offset
    __shared__ int s[SCAN_B];
    int i = blockIdx.x * SCAN_B + threadIdx.x;
    int d = (i < NODES) ? g_deg[i] : 0;
    s[threadIdx.x] = d;
    __syncthreads();
    for (int off = 1; off < SCAN_B; off <<= 1) {
        int v = (threadIdx.x >= off) ? s[threadIdx.x - off] : 0;
        __syncthreads();
        s[threadIdx.x] += v;
        __syncthreads();
    }
    if (i < NODES) {
        int excl = g_boff[blockIdx.x] + s[threadIdx.x] - d;
        g_rowptr[i] = excl;
        g_cursor[i] = excl;
        if (i == NODES - 1) g_rowptr[NODES] = g_boff[blockIdx.x] + s[threadIdx.x];
    }
}

__global__ void fill_kernel(const int* __restrict__ ei) {
    int e = blockIdx.x * blockDim.x + threadIdx.x;
    if (e >= EDGES) return;
    int src = __ldg(&ei[e]);
    int dst = __ldg(&ei[EDGES + e]);
    if ((unsigned)src >= NODES || (unsigned)dst >= NODES) return;
    int p = atomicAdd(&g_cursor[dst], 1);
    g_col[p] = src;
}

// ---------------------------------------------------------------------------
// Gather (fp16 messages): half-warp (16 lanes) per dst node; lane c reads
// uint2 (4 halves = dims 4c..4c+3) per neighbor, accumulates in fp32,
// writes fp32 mean. Bytes per edge: 128 (was 256). 8-way unrolled.
// ---------------------------------------------------------------------------
__global__ void gather_kernel(const __half* __restrict__ feat16) {
    long long t = (long long)blockIdx.x * blockDim.x + threadIdx.x;
    if (t >= (long long)NODES * 16) return;
    int node = (int)(t >> 4);
    int c    = (int)(t & 15);

    int start = __ldg(&g_rowptr[node]);
    int end   = __ldg(&g_rowptr[node + 1]);

    float4 acc = make_float4(0.f, 0.f, 0.f, 0.f);
    int p = start;

#define ACC_EDGE(uu)                                            \
    {  __half2 ph0 = *reinterpret_cast<__half2*>(&(uu).x);      \
       __half2 ph1 = *reinterpret_cast<__half2*>(&(uu).y);      \
       float2 f0 = __half22float2(ph0);                         \
       float2 f1 = __half22float2(ph1);                         \
       acc.x += f0.x; acc.y += f0.y; acc.z += f1.x; acc.w += f1.y; }

    for (; p + 8 <= end; p += 8) {
        int s0 = __ldg(&g_col[p + 0]);
        int s1 = __ldg(&g_col[p + 1]);
        int s2 = __ldg(&g_col[p + 2]);
        int s3 = __ldg(&g_col[p + 3]);
        int s4 = __ldg(&g_col[p + 4]);
        int s5 = __ldg(&g_col[p + 5]);
        int s6 = __ldg(&g_col[p + 6]);
        int s7 = __ldg(&g_col[p + 7]);
        uint2 u0 = __ldg(((const uint2*)(feat16 + (size_t)s0 * DIM)) + c);
        uint2 u1 = __ldg(((const uint2*)(feat16 + (size_t)s1 * DIM)) + c);
        uint2 u2 = __ldg(((const uint2*)(feat16 + (size_t)s2 * DIM)) + c);
        uint2 u3 = __ldg(((const uint2*)(feat16 + (size_t)s3 * DIM)) + c);
        uint2 u4 = __ldg(((const uint2*)(feat16 + (size_t)s4 * DIM)) + c);
        uint2 u5 = __ldg(((const uint2*)(feat16 + (size_t)s5 * DIM)) + c);
        uint2 u6 = __ldg(((const uint2*)(feat16 + (size_t)s6 * DIM)) + c);
        uint2 u7 = __ldg(((const uint2*)(feat16 + (size_t)s7 * DIM)) + c);
        ACC_EDGE(u0); ACC_EDGE(u1); ACC_EDGE(u2); ACC_EDGE(u3);
        ACC_EDGE(u4); ACC_EDGE(u5); ACC_EDGE(u6); ACC_EDGE(u7);
    }
    for (; p < end; p++) {
        int s = __ldg(&g_col[p]);
        uint2 u = __ldg(((const uint2*)(feat16 + (size_t)s * DIM)) + c);
        ACC_EDGE(u);
    }
#undef ACC_EDGE

    float inv = 1.0f / fmaxf((float)(end - start), 1.0f);
    acc.x *= inv; acc.y *= inv; acc.z *= inv; acc.w *= inv;
    ((float4*)(g_agg + (size_t)node * DIM))[c] = acc;
}

// ---------------------------------------------------------------------------
// Node transform (register-tiled): thread = 4 nodes x 4 dims, 64 nodes/block.
// Weights transposed into smem (pitch 65). Activations via gmem float4
// broadcast. Optionally writes an fp16 shadow of the output (layer 1 -> h16).
// ---------------------------------------------------------------------------
#define TN 64

template <bool APPLY_TANH, bool WRITE_H16>
__global__ void __launch_bounds__(256) transform_kernel(
        const float* __restrict__ agg,
        const float* __restrict__ xin,
        const float* __restrict__ Wl,
        const float* __restrict__ bl,
        const float* __restrict__ Wr,
        float* __restrict__ out) {
    __shared__ float sW[128 * 65];

    int tid = threadIdx.x;
    for (int i = tid; i < DIM * DIM; i += 256) {
        int dout = i >> 6, k = i & 63;
        sW[k * 65 + dout]        = __ldg(&Wl[i]);
        sW[(64 + k) * 65 + dout] = __ldg(&Wr[i]);
    }
    __syncthreads();

    int dt = tid & 15;
    int nt = tid >> 4;
    int d  = dt * 4;
    int n0 = blockIdx.x * TN + nt * 4;

    const float4* arow[4];
    const float4* xrow[4];
#pragma unroll
    for (int j = 0; j < 4; j++) {
        int n = n0 + j; if (n >= NODES) n = NODES - 1;
        arow[j] = (const float4*)(agg + (size_t)n * DIM);
        xrow[j] = (const float4*)(xin + (size_t)n * DIM);
    }

    float acc[4][4];
#pragma unroll
    for (int j = 0; j < 4; j++)
#pragma unroll
        for (int q = 0; q < 4; q++) acc[j][q] = 0.0f;

#pragma unroll
    for (int kq = 0; kq < 16; kq++) {
        float4 a0 = __ldg(arow[0] + kq);
        float4 a1 = __ldg(arow[1] + kq);
        float4 a2 = __ldg(arow[2] + kq);
        float4 a3 = __ldg(arow[3] + kq);
        const float av[4][4] = {{a0.x,a0.y,a0.z,a0.w},{a1.x,a1.y,a1.z,a1.w},
                                {a2.x,a2.y,a2.z,a2.w},{a3.x,a3.y,a3.z,a3.w}};
#pragma unroll
        for (int kk = 0; kk < 4; kk++) {
            int k = kq * 4 + kk;
            float w0 = sW[k * 65 + d + 0];
            float w1 = sW[k * 65 + d + 1];
            float w2 = sW[k * 65 + d + 2];
            float w3 = sW[k * 65 + d + 3];
#pragma unroll
            for (int j = 0; j < 4; j++) {
                acc[j][0] += av[j][kk] * w0;
                acc[j][1] += av[j][kk] * w1;
                acc[j][2] += av[j][kk] * w2;
                acc[j][3] += av[j][kk] * w3;
            }
        }
    }
#pragma unroll
    for (int kq = 0; kq < 16; kq++) {
        float4 a0 = __ldg(xrow[0] + kq);
        float4 a1 = __ldg(xrow[1] + kq);
        float4 a2 = __ldg(xrow[2] + kq);
        float4 a3 = __ldg(xrow[3] + kq);
        const float av[4][4] = {{a0.x,a0.y,a0.z,a0.w},{a1.x,a1.y,a1.z,a1.w},
                                {a2.x,a2.y,a2.z,a2.w},{a3.x,a3.y,a3.z,a3.w}};
#pragma unroll
        for (int kk = 0; kk < 4; kk++) {
            int k = 64 + kq * 4 + kk;
            float w0 = sW[k * 65 + d + 0];
            float w1 = sW[k * 65 + d + 1];
            float w2 = sW[k * 65 + d + 2];
            float w3 = sW[k * 65 + d + 3];
#pragma unroll
            for (int j = 0; j < 4; j++) {
                acc[j][0] += av[j][kk] * w0;
                acc[j][1] += av[j][kk] * w1;
                acc[j][2] += av[j][kk] * w2;
                acc[j][3] += av[j][kk] * w3;
            }
        }
    }

    float b0 = __ldg(&bl[d + 0]);
    float b1 = __ldg(&bl[d + 1]);
    float b2 = __ldg(&bl[d + 2]);
    float b3 = __ldg(&bl[d + 3]);

#pragma unroll
    for (int j = 0; j < 4; j++) {
        int n = n0 + j;
        if (n >= NODES) break;
        float4 r;
        r.x = acc[j][0] + b0;
        r.y = acc[j][1] + b1;
        r.z = acc[j][2] + b2;
        r.w = acc[j][3] + b3;
        if (APPLY_TANH) {
            r.x = tanhf(r.x); r.y = tanhf(r.y);
            r.z = tanhf(r.z); r.w = tanhf(r.w);
        }
        ((float4*)(out + (size_t)n * DIM))[dt] = r;
        if (WRITE_H16) {
            __half2* hp = (__half2*)(g_h16 + (size_t)n * DIM);
            hp[dt * 2 + 0] = __floats2half2_rn(r.x, r.y);
            hp[dt * 2 + 1] = __floats2half2_rn(r.z, r.w);
        }
    }
}

// ---------------------------------------------------------------------------
// Launch
// ---------------------------------------------------------------------------
extern "C" void kernel_launch(void* const* d_in, const int* in_sizes, int n_in,
                              void* d_out, int out_size) {
    const float* x    = (const float*)d_in[0];
    const int*   ei   = (const int*)d_in[1];
    const float* W_l1 = (const float*)d_in[2];
    const float* b_l1 = (const float*)d_in[3];
    const float* W_r1 = (const float*)d_in[4];
    const float* W_l2 = (const float*)d_in[5];
    const float* b_l2 = (const float*)d_in[6];
    const float* W_r2 = (const float*)d_in[7];
    float* out = (float*)d_out;

    float*  agg; cudaGetSymbolAddress((void**)&agg, g_agg);
    float*  h;   cudaGetSymbolAddress((void**)&h,   g_h);
    __half* x16; cudaGetSymbolAddress((void**)&x16, g_x16);
    __half* h16; cudaGetSymbolAddress((void**)&h16, g_h16);

    const int EB = 256, EG = (EDGES + EB - 1) / EB;
    const int CG = (NODES * DIM / 4 + 255) / 256;
    const int GG = (int)(((long long)NODES * 16 + 255) / 256);
    const int TG = (NODES + TN - 1) / TN;

    // Stage x as fp16 + build CSR (reused by both layers)
    convert_kernel<<<CG, 256>>>(x);
    zero_deg_kernel<<<(NODES + 255) / 256, 256>>>();
    hist_kernel<<<EG, EB>>>(ei);
    scanA_kernel<<<NB, SCAN_B>>>();
    scanB_kernel<<<1, 128>>>();
    scanC_kernel<<<NB, SCAN_B>>>();
    fill_kernel<<<EG, EB>>>(ei);

    // Layer 1
    gather_kernel<<<GG, 256>>>(x16);
    transform_kernel<true, true><<<TG, 256>>>(agg, x, W_l1, b_l1, W_r1, h);

    // Layer 2
    gather_kernel<<<GG, 256>>>(h16);
    transform_kernel<false, false><<<TG, 256>>>(agg, h, W_l2, b_l2, W_r2, out);
}